// round 5
// baseline (speedup 1.0000x reference)
#include <cuda_runtime.h>
#include <cstdint>

#define L_SEQ   1024
#define KNN     48
#define H       128
#define N_EDGES (L_SEQ * KNN)     // 49152
#define N_TILES (N_EDGES / 128)   // 384
#define GRID_MAIN 148
#define NTHREADS 512

__device__ float d_hv[L_SEQ * H];   // LN+W1 output (512 KB scratch)

// smem byte offsets (main kernel)
#define SM_W2HI 0
#define SM_W2LO 32768
#define SM_PHI  65536
#define SM_PLO  98304
#define SM_B2   131072
#define SM_TOTAL (131072 + 512 + 128)   // 131712 B

// ---------------------------------------------------------------------------
// helpers
// ---------------------------------------------------------------------------
__device__ __forceinline__ uint32_t smem_to_u32(const void* p) {
    uint32_t a;
    asm("{ .reg .u64 t; cvta.to.shared.u64 t, %1; cvt.u32.u64 %0, t; }"
        : "=r"(a) : "l"(p));
    return a;
}

// XOR swizzle on 16B chunks within a 256B row (conflict-free ldmatrix/STS)
__device__ __forceinline__ uint32_t swz(uint32_t row, uint32_t chunk) {
    return (chunk & 8u) | ((chunk ^ row) & 7u);
}

// split (a,b) fp32 pair into packed bf16x2 hi + bf16x2 lo (a -> low 16 bits)
__device__ __forceinline__ void split2(float a, float b, uint32_t& hi, uint32_t& lo) {
    uint32_t h;
    asm("cvt.rn.bf16x2.f32 %0, %1, %2;" : "=r"(h) : "f"(b), "f"(a));
    float ha = __uint_as_float(h << 16);
    float hb = __uint_as_float(h & 0xFFFF0000u);
    float la = a - ha;
    float lb = b - hb;
    asm("cvt.rn.bf16x2.f32 %0, %1, %2;" : "=r"(lo) : "f"(lb), "f"(la));
    hi = h;
}

__device__ __forceinline__ void ldsm_x4(uint32_t* r, uint32_t addr) {
    asm volatile("ldmatrix.sync.aligned.m8n8.x4.shared.b16 {%0,%1,%2,%3}, [%4];"
                 : "=r"(r[0]), "=r"(r[1]), "=r"(r[2]), "=r"(r[3]) : "r"(addr));
}

__device__ __forceinline__ void mma_bf16(float* c, const uint32_t* a,
                                         uint32_t b0, uint32_t b1) {
    asm volatile("mma.sync.aligned.m16n8k16.row.col.f32.bf16.bf16.f32 "
                 "{%0,%1,%2,%3}, {%4,%5,%6,%7}, {%8,%9}, {%0,%1,%2,%3};"
                 : "+f"(c[0]), "+f"(c[1]), "+f"(c[2]), "+f"(c[3])
                 : "r"(a[0]), "r"(a[1]), "r"(a[2]), "r"(a[3]), "r"(b0), "r"(b1));
}

// ---------------------------------------------------------------------------
// Kernel 1: LayerNorm + Linear1 -> d_hv.  8 rows/block, 128 threads, 128 blocks.
// ---------------------------------------------------------------------------
__global__ void __launch_bounds__(128) ln_w1_kernel(
    const float* __restrict__ hV, const float* __restrict__ W1,
    const float* __restrict__ b1, const float* __restrict__ ln_scale,
    const float* __restrict__ ln_bias) {
    __shared__ float xs[8][H];
    int t = threadIdx.x, w = t >> 5, lane = t & 31;
    int i0 = blockIdx.x * 8;

    float4 g = reinterpret_cast<const float4*>(ln_scale)[lane];
    float4 c = reinterpret_cast<const float4*>(ln_bias)[lane];

    #pragma unroll
    for (int rr = 0; rr < 2; rr++) {
        int r = w + rr * 4;
        float4 x = reinterpret_cast<const float4*>(hV + (size_t)(i0 + r) * H)[lane];
        float s = x.x + x.y + x.z + x.w;
        #pragma unroll
        for (int off = 16; off; off >>= 1) s += __shfl_xor_sync(~0u, s, off);
        float mu = s * (1.0f / H);
        float4 d = make_float4(x.x - mu, x.y - mu, x.z - mu, x.w - mu);
        float sq = d.x * d.x + d.y * d.y + d.z * d.z + d.w * d.w;
        #pragma unroll
        for (int off = 16; off; off >>= 1) sq += __shfl_xor_sync(~0u, sq, off);
        float rs = rsqrtf(sq * (1.0f / H) + 1e-5f);
        float4 o = make_float4(d.x * rs * g.x + c.x, d.y * rs * g.y + c.y,
                               d.z * rs * g.z + c.z, d.w * rs * g.w + c.w);
        reinterpret_cast<float4*>(xs[r])[lane] = o;
    }
    __syncthreads();

    float acc[8];
    float bt = b1[t];
    #pragma unroll
    for (int r = 0; r < 8; r++) acc[r] = bt;
    const float4* wrow = reinterpret_cast<const float4*>(W1 + (size_t)t * H);
    #pragma unroll 4
    for (int q = 0; q < H / 4; q++) {
        float4 w4 = wrow[q];
        #pragma unroll
        for (int r = 0; r < 8; r++) {
            float4 x4 = reinterpret_cast<const float4*>(xs[r])[q];
            acc[r] += w4.x * x4.x + w4.y * x4.y + w4.z * x4.z + w4.w * x4.w;
        }
    }
    #pragma unroll
    for (int r = 0; r < 8; r++) d_hv[(size_t)(i0 + r) * H + t] = acc[r];
}

// ---------------------------------------------------------------------------
// Kernel 2: C[49152,128] = P @ W2^T via mma.sync bf16, 3-term split.
// 512 threads = 16 warps as 8(m) x 2(n): warp tile m16 x n64, K=128.
// ---------------------------------------------------------------------------
__global__ void __launch_bounds__(NTHREADS, 1) outer_w2_mma_kernel(
    const int* __restrict__ Eidx, const float* __restrict__ W2,
    const float* __restrict__ b2, float* __restrict__ out) {
    extern __shared__ char smemc[];
    const uint32_t sb = smem_to_u32(smemc);
    int t = threadIdx.x;
    int warp = t >> 5, lane = t & 31;
    int wm = warp >> 1;     // 0..7  m16 tile
    int wn = warp & 1;      // 0..1  n64 half

    // ---- stage W2 hi/lo (bf16, swizzled [o][h]) + b2 ----
    #pragma unroll
    for (int it = 0; it < 4; it++) {
        int g = it * NTHREADS + t;     // 0..2047 chunk index
        int o = g >> 4;                // output feature row
        int ch = g & 15;               // 16B chunk within row
        const float4* w = reinterpret_cast<const float4*>(W2 + (size_t)o * H + ch * 8);
        float4 w0 = w[0], w1 = w[1];
        uint4 hi4, lo4;
        split2(w0.x, w0.y, hi4.x, lo4.x);
        split2(w0.z, w0.w, hi4.y, lo4.y);
        split2(w1.x, w1.y, hi4.z, lo4.z);
        split2(w1.z, w1.w, hi4.w, lo4.w);
        uint32_t off = (uint32_t)o * 256 + swz(o, ch) * 16;
        *reinterpret_cast<uint4*>(smemc + SM_W2HI + off) = hi4;
        *reinterpret_cast<uint4*>(smemc + SM_W2LO + off) = lo4;
    }
    if (t < 128) reinterpret_cast<float*>(smemc + SM_B2)[t] = b2[t];
    __syncthreads();

    // ldmatrix lane-address components
    const uint32_t m_in_tile = (uint32_t)(wm * 16 + (lane & 15));
    const uint32_t a_rowoff  = m_in_tile * 256;
    const uint32_t a_sel     = (uint32_t)(lane >> 4);
    const uint32_t b_row7    = (uint32_t)(lane & 7);
    const uint32_t b_rowoff  = b_row7 * 256;
    const uint32_t b_sel     = (uint32_t)(lane >> 3);

    for (int tile = blockIdx.x; tile < N_TILES; tile += gridDim.x) {
        // ---- build P hi/lo in smem (gather); 4 threads per edge row ----
        {
            int m  = t >> 2;             // edge row in tile (0..127)
            int q4 = t & 3;              // h quarter (32 values)
            int e = tile * 128 + m;
            int i = (int)((unsigned)e / KNN);
            int j = __ldg(Eidx + e);
            const float4* pi = reinterpret_cast<const float4*>(
                d_hv + (size_t)i * H + q4 * 32);
            const float4* pj = reinterpret_cast<const float4*>(
                d_hv + (size_t)j * H + q4 * 32);
            uint32_t rowbase = (uint32_t)m * 256;
            #pragma unroll
            for (int q = 0; q < 4; q++) {
                float4 x0 = pi[2 * q], x1 = pi[2 * q + 1];
                float4 y0 = pj[2 * q], y1 = pj[2 * q + 1];
                uint4 hi4, lo4;
                split2(x0.x * y0.x, x0.y * y0.y, hi4.x, lo4.x);
                split2(x0.z * y0.z, x0.w * y0.w, hi4.y, lo4.y);
                split2(x1.x * y1.x, x1.y * y1.y, hi4.z, lo4.z);
                split2(x1.z * y1.z, x1.w * y1.w, hi4.w, lo4.w);
                uint32_t off = rowbase + swz((uint32_t)m, (uint32_t)(q4 * 4 + q)) * 16;
                *reinterpret_cast<uint4*>(smemc + SM_PHI + off) = hi4;
                *reinterpret_cast<uint4*>(smemc + SM_PLO + off) = lo4;
            }
        }
        __syncthreads();

        // ---- warp GEMM: m16 x n64, K=128, 3-term bf16 split ----
        float acc[8][4];
        #pragma unroll
        for (int nt = 0; nt < 8; nt++)
            #pragma unroll
            for (int q = 0; q < 4; q++) acc[nt][q] = 0.0f;

        #pragma unroll
        for (int kp = 0; kp < 4; kp++) {        // k32 steps
            uint32_t ah[2][4], al[2][4];
            #pragma unroll
            for (int ss = 0; ss < 2; ss++) {
                uint32_t chunkA = (uint32_t)(4 * kp + 2 * ss) + a_sel;
                uint32_t aaddr = sb + SM_PHI + a_rowoff + swz(m_in_tile, chunkA) * 16;
                ldsm_x4(ah[ss], aaddr);
                ldsm_x4(al[ss], aaddr + (SM_PLO - SM_PHI));
            }
            uint32_t chunkB = (uint32_t)(kp * 4) + b_sel;
            uint32_t bcol = swz(b_row7, chunkB) * 16;
            #pragma unroll
            for (int nt = 0; nt < 8; nt++) {
                uint32_t o8 = (uint32_t)(wn * 8 + nt);     // n8 tile index
                uint32_t baddr = sb + SM_W2HI + o8 * 2048 + b_rowoff + bcol;
                uint32_t bh[4], bl[4];
                ldsm_x4(bh, baddr);
                ldsm_x4(bl, baddr + (SM_W2LO - SM_W2HI));
                mma_bf16(acc[nt], ah[0], bh[0], bh[1]);   // hi*hi (k lo half)
                mma_bf16(acc[nt], ah[0], bl[0], bl[1]);   // hi*lo
                mma_bf16(acc[nt], al[0], bh[0], bh[1]);   // lo*hi
                mma_bf16(acc[nt], ah[1], bh[2], bh[3]);   // hi*hi (k hi half)
                mma_bf16(acc[nt], ah[1], bl[2], bl[3]);
                mma_bf16(acc[nt], al[1], bh[2], bh[3]);
            }
        }

        // ---- epilogue: + b2, store ----
        {
            int r0 = tile * 128 + wm * 16 + (lane >> 2);
            int cbase = wn * 64 + (lane & 3) * 2;
            float* orow0 = out + (size_t)r0 * H;
            float* orow1 = orow0 + 8 * H;
            #pragma unroll
            for (int nt = 0; nt < 8; nt++) {
                float2 bb = *reinterpret_cast<const float2*>(
                    smemc + SM_B2 + (wn * 64 + nt * 8 + (lane & 3) * 2) * 4);
                float2 v0 = make_float2(acc[nt][0] + bb.x, acc[nt][1] + bb.y);
                float2 v1 = make_float2(acc[nt][2] + bb.x, acc[nt][3] + bb.y);
                *reinterpret_cast<float2*>(orow0 + nt * 8 + cbase) = v0;
                *reinterpret_cast<float2*>(orow1 + nt * 8 + cbase) = v1;
            }
        }
        __syncthreads();   // all warps done reading sP before next build
    }
}

// ---------------------------------------------------------------------------
extern "C" void kernel_launch(void* const* d_in, const int* in_sizes, int n_in,
                              void* d_out, int out_size) {
    const float* hV       = (const float*)d_in[0];
    const int*   Eidx     = (const int*)d_in[1];
    const float* W1       = (const float*)d_in[2];
    const float* b1       = (const float*)d_in[3];
    const float* W2       = (const float*)d_in[4];
    const float* b2       = (const float*)d_in[5];
    const float* ln_scale = (const float*)d_in[6];
    const float* ln_bias  = (const float*)d_in[7];
    float* out = (float*)d_out;

    cudaFuncSetAttribute(outer_w2_mma_kernel,
                         cudaFuncAttributeMaxDynamicSharedMemorySize, SM_TOTAL);

    ln_w1_kernel<<<L_SEQ / 8, 128>>>(hV, W1, b1, ln_scale, ln_bias);
    outer_w2_mma_kernel<<<GRID_MAIN, NTHREADS, SM_TOTAL>>>(Eidx, W2, b2, out);
}

// round 6
// speedup vs baseline: 1.0590x; 1.0590x over previous
#include <cuda_runtime.h>
#include <cstdint>

#define L_SEQ   1024
#define KNN     48
#define H       128
#define N_EDGES (L_SEQ * KNN)       // 49152
#define TILE_E  192
#define N_TILES (N_EDGES / TILE_E)  // 256
#define GRID_MAIN 148
#define NTHREADS 384

__device__ float d_hv[L_SEQ * H];   // LN+W1 output (512 KB scratch)

// smem byte offsets (main kernel)
#define SM_W2HI 0
#define SM_W2LO 32768
#define SM_PHI  65536
#define SM_PLO  (65536 + TILE_E * 256)            // 114688
#define SM_B2   (SM_PLO + TILE_E * 256)           // 163840
#define SM_TOTAL (SM_B2 + 512 + 128)              // 164480 B

// ---------------------------------------------------------------------------
// helpers
// ---------------------------------------------------------------------------
__device__ __forceinline__ uint32_t smem_to_u32(const void* p) {
    uint32_t a;
    asm("{ .reg .u64 t; cvta.to.shared.u64 t, %1; cvt.u32.u64 %0, t; }"
        : "=r"(a) : "l"(p));
    return a;
}

// XOR swizzle on 16B chunks within a 256B row (conflict-free ldmatrix/STS)
__device__ __forceinline__ uint32_t swz(uint32_t row, uint32_t chunk) {
    return (chunk & 8u) | ((chunk ^ row) & 7u);
}

// split (a,b) fp32 pair into packed bf16x2 hi + bf16x2 lo (a -> low 16 bits)
__device__ __forceinline__ void split2(float a, float b, uint32_t& hi, uint32_t& lo) {
    uint32_t h;
    asm("cvt.rn.bf16x2.f32 %0, %1, %2;" : "=r"(h) : "f"(b), "f"(a));
    float ha = __uint_as_float(h << 16);
    float hb = __uint_as_float(h & 0xFFFF0000u);
    float la = a - ha;
    float lb = b - hb;
    asm("cvt.rn.bf16x2.f32 %0, %1, %2;" : "=r"(lo) : "f"(lb), "f"(la));
    hi = h;
}

__device__ __forceinline__ void ldsm_x4(uint32_t* r, uint32_t addr) {
    asm volatile("ldmatrix.sync.aligned.m8n8.x4.shared.b16 {%0,%1,%2,%3}, [%4];"
                 : "=r"(r[0]), "=r"(r[1]), "=r"(r[2]), "=r"(r[3]) : "r"(addr));
}

__device__ __forceinline__ void mma_bf16(float* c, const uint32_t* a,
                                         uint32_t b0, uint32_t b1) {
    asm volatile("mma.sync.aligned.m16n8k16.row.col.f32.bf16.bf16.f32 "
                 "{%0,%1,%2,%3}, {%4,%5,%6,%7}, {%8,%9}, {%0,%1,%2,%3};"
                 : "+f"(c[0]), "+f"(c[1]), "+f"(c[2]), "+f"(c[3])
                 : "r"(a[0]), "r"(a[1]), "r"(a[2]), "r"(a[3]), "r"(b0), "r"(b1));
}

// ---------------------------------------------------------------------------
// Kernel 1: LayerNorm + Linear1 -> d_hv.  4 rows/block, 128 threads, 256 blocks.
// ---------------------------------------------------------------------------
__global__ void __launch_bounds__(128) ln_w1_kernel(
    const float* __restrict__ hV, const float* __restrict__ W1,
    const float* __restrict__ b1, const float* __restrict__ ln_scale,
    const float* __restrict__ ln_bias) {
    __shared__ float xs[4][H];
    int t = threadIdx.x, w = t >> 5, lane = t & 31;
    int i0 = blockIdx.x * 4;

    float4 g = reinterpret_cast<const float4*>(ln_scale)[lane];
    float4 c = reinterpret_cast<const float4*>(ln_bias)[lane];

    {
        int r = w;   // one row per warp
        float4 x = reinterpret_cast<const float4*>(hV + (size_t)(i0 + r) * H)[lane];
        float s = x.x + x.y + x.z + x.w;
        #pragma unroll
        for (int off = 16; off; off >>= 1) s += __shfl_xor_sync(~0u, s, off);
        float mu = s * (1.0f / H);
        float4 d = make_float4(x.x - mu, x.y - mu, x.z - mu, x.w - mu);
        float sq = d.x * d.x + d.y * d.y + d.z * d.z + d.w * d.w;
        #pragma unroll
        for (int off = 16; off; off >>= 1) sq += __shfl_xor_sync(~0u, sq, off);
        float rs = rsqrtf(sq * (1.0f / H) + 1e-5f);
        float4 o = make_float4(d.x * rs * g.x + c.x, d.y * rs * g.y + c.y,
                               d.z * rs * g.z + c.z, d.w * rs * g.w + c.w);
        reinterpret_cast<float4*>(xs[r])[lane] = o;
    }
    __syncthreads();

    float acc[4];
    float bt = b1[t];
    #pragma unroll
    for (int r = 0; r < 4; r++) acc[r] = bt;
    const float4* wrow = reinterpret_cast<const float4*>(W1 + (size_t)t * H);
    #pragma unroll 8
    for (int q = 0; q < H / 4; q++) {
        float4 w4 = wrow[q];
        #pragma unroll
        for (int r = 0; r < 4; r++) {
            float4 x4 = reinterpret_cast<const float4*>(xs[r])[q];
            acc[r] += w4.x * x4.x + w4.y * x4.y + w4.z * x4.z + w4.w * x4.w;
        }
    }
    #pragma unroll
    for (int r = 0; r < 4; r++) d_hv[(size_t)(i0 + r) * H + t] = acc[r];
}

// ---------------------------------------------------------------------------
// Kernel 2: C[49152,128] = P @ W2^T via mma.sync bf16, 3-term split.
// 384 threads = 12 warps as 6(m) x 2(n): warp tile m32 x n64, K=128.
// Each B fragment feeds both m16 subtiles (halves B LDSM redundancy).
// ---------------------------------------------------------------------------
__global__ void __launch_bounds__(NTHREADS, 1) outer_w2_mma_kernel(
    const int* __restrict__ Eidx, const float* __restrict__ W2,
    const float* __restrict__ b2, float* __restrict__ out) {
    extern __shared__ char smemc[];
    const uint32_t sb = smem_to_u32(smemc);
    int t = threadIdx.x;
    int warp = t >> 5, lane = t & 31;
    int wm = warp >> 1;     // 0..5  m32 tile
    int wn = warp & 1;      // 0..1  n64 half

    // ---- stage W2 hi/lo (bf16, swizzled [o][h]) + b2 ----
    for (int g = t; g < 2048; g += NTHREADS) {
        int o = g >> 4;                // output feature row
        int ch = g & 15;               // 16B chunk within row
        const float4* w = reinterpret_cast<const float4*>(W2 + (size_t)o * H + ch * 8);
        float4 w0 = w[0], w1 = w[1];
        uint4 hi4, lo4;
        split2(w0.x, w0.y, hi4.x, lo4.x);
        split2(w0.z, w0.w, hi4.y, lo4.y);
        split2(w1.x, w1.y, hi4.z, lo4.z);
        split2(w1.z, w1.w, hi4.w, lo4.w);
        uint32_t off = (uint32_t)o * 256 + swz(o, ch) * 16;
        *reinterpret_cast<uint4*>(smemc + SM_W2HI + off) = hi4;
        *reinterpret_cast<uint4*>(smemc + SM_W2LO + off) = lo4;
    }
    if (t < 128) reinterpret_cast<float*>(smemc + SM_B2)[t] = b2[t];
    __syncthreads();

    // ldmatrix lane-address components for the two m16 subtiles
    const uint32_t m0 = (uint32_t)(wm * 32 + (lane & 15));
    const uint32_t m1 = m0 + 16;
    const uint32_t a_sel  = (uint32_t)(lane >> 4);
    const uint32_t b_row7 = (uint32_t)(lane & 7);
    const uint32_t b_rowoff = b_row7 * 256;
    const uint32_t b_sel  = (uint32_t)(lane >> 3);

    for (int tile = blockIdx.x; tile < N_TILES; tile += gridDim.x) {
        // ---- build P hi/lo in smem (gather); 2 threads per edge row ----
        {
            int m = t >> 1;                  // edge row in tile (0..191)
            int half = t & 1;                // h half (64 each)
            int e = tile * TILE_E + m;
            int i = (int)((unsigned)e / KNN);
            int j = __ldg(Eidx + e);
            const float4* pi = reinterpret_cast<const float4*>(
                d_hv + (size_t)i * H + half * 64);
            const float4* pj = reinterpret_cast<const float4*>(
                d_hv + (size_t)j * H + half * 64);
            uint32_t rowbase = (uint32_t)m * 256;
            #pragma unroll
            for (int q = 0; q < 8; q++) {
                float4 x0 = pi[2 * q], x1 = pi[2 * q + 1];
                float4 y0 = pj[2 * q], y1 = pj[2 * q + 1];
                uint4 hi4, lo4;
                split2(x0.x * y0.x, x0.y * y0.y, hi4.x, lo4.x);
                split2(x0.z * y0.z, x0.w * y0.w, hi4.y, lo4.y);
                split2(x1.x * y1.x, x1.y * y1.y, hi4.z, lo4.z);
                split2(x1.z * y1.z, x1.w * y1.w, hi4.w, lo4.w);
                uint32_t off = rowbase + swz((uint32_t)m, (uint32_t)(half * 8 + q)) * 16;
                *reinterpret_cast<uint4*>(smemc + SM_PHI + off) = hi4;
                *reinterpret_cast<uint4*>(smemc + SM_PLO + off) = lo4;
            }
        }
        __syncthreads();

        // ---- warp GEMM: m32 x n64, K=128, 3-term bf16 split ----
        float acc[2][8][4];
        #pragma unroll
        for (int s = 0; s < 2; s++)
            #pragma unroll
            for (int nt = 0; nt < 8; nt++)
                #pragma unroll
                for (int q = 0; q < 4; q++) acc[s][nt][q] = 0.0f;

        #pragma unroll
        for (int kp = 0; kp < 4; kp++) {        // k32 steps
            uint32_t ah[2][2][4], al[2][2][4];  // [subtile][k16 half]
            #pragma unroll
            for (int s = 0; s < 2; s++) {
                uint32_t mrow = s ? m1 : m0;
                uint32_t rowoff = mrow * 256;
                #pragma unroll
                for (int ss = 0; ss < 2; ss++) {
                    uint32_t chunkA = (uint32_t)(4 * kp + 2 * ss) + a_sel;
                    uint32_t aaddr = sb + SM_PHI + rowoff + swz(mrow, chunkA) * 16;
                    ldsm_x4(ah[s][ss], aaddr);
                    ldsm_x4(al[s][ss], aaddr + (SM_PLO - SM_PHI));
                }
            }
            uint32_t chunkB = (uint32_t)(kp * 4) + b_sel;
            uint32_t bcol = swz(b_row7, chunkB) * 16;
            #pragma unroll
            for (int nt = 0; nt < 8; nt++) {
                uint32_t o8 = (uint32_t)(wn * 8 + nt);     // n8 tile index
                uint32_t baddr = sb + SM_W2HI + o8 * 2048 + b_rowoff + bcol;
                uint32_t bh[4], bl[4];
                ldsm_x4(bh, baddr);
                ldsm_x4(bl, baddr + (SM_W2LO - SM_W2HI));
                #pragma unroll
                for (int s = 0; s < 2; s++) {
                    mma_bf16(acc[s][nt], ah[s][0], bh[0], bh[1]);  // hi*hi (k lo)
                    mma_bf16(acc[s][nt], ah[s][0], bl[0], bl[1]);  // hi*lo
                    mma_bf16(acc[s][nt], al[s][0], bh[0], bh[1]);  // lo*hi
                    mma_bf16(acc[s][nt], ah[s][1], bh[2], bh[3]);  // hi*hi (k hi)
                    mma_bf16(acc[s][nt], ah[s][1], bl[2], bl[3]);
                    mma_bf16(acc[s][nt], al[s][1], bh[2], bh[3]);
                }
            }
        }

        // ---- epilogue: + b2, store ----
        #pragma unroll
        for (int s = 0; s < 2; s++) {
            int r0 = tile * TILE_E + wm * 32 + s * 16 + (lane >> 2);
            int cbase = wn * 64 + (lane & 3) * 2;
            float* orow0 = out + (size_t)r0 * H;
            float* orow1 = orow0 + 8 * H;
            #pragma unroll
            for (int nt = 0; nt < 8; nt++) {
                float2 bb = *reinterpret_cast<const float2*>(
                    smemc + SM_B2 + (wn * 64 + nt * 8 + (lane & 3) * 2) * 4);
                float2 v0 = make_float2(acc[s][nt][0] + bb.x, acc[s][nt][1] + bb.y);
                float2 v1 = make_float2(acc[s][nt][2] + bb.x, acc[s][nt][3] + bb.y);
                *reinterpret_cast<float2*>(orow0 + nt * 8 + cbase) = v0;
                *reinterpret_cast<float2*>(orow1 + nt * 8 + cbase) = v1;
            }
        }
        __syncthreads();   // all warps done reading sP before next build
    }
}

// ---------------------------------------------------------------------------
extern "C" void kernel_launch(void* const* d_in, const int* in_sizes, int n_in,
                              void* d_out, int out_size) {
    const float* hV       = (const float*)d_in[0];
    const int*   Eidx     = (const int*)d_in[1];
    const float* W1       = (const float*)d_in[2];
    const float* b1       = (const float*)d_in[3];
    const float* W2       = (const float*)d_in[4];
    const float* b2       = (const float*)d_in[5];
    const float* ln_scale = (const float*)d_in[6];
    const float* ln_bias  = (const float*)d_in[7];
    float* out = (float*)d_out;

    cudaFuncSetAttribute(outer_w2_mma_kernel,
                         cudaFuncAttributeMaxDynamicSharedMemorySize, SM_TOTAL);

    ln_w1_kernel<<<L_SEQ / 4, 128>>>(hV, W1, b1, ln_scale, ln_bias);
    outer_w2_mma_kernel<<<GRID_MAIN, NTHREADS, SM_TOTAL>>>(Eidx, W2, b2, out);
}

// round 8
// speedup vs baseline: 1.0607x; 1.0016x over previous
#include <cuda_runtime.h>
#include <cstdint>

#define L_SEQ   1024
#define KNN     48
#define H       128
#define N_EDGES (L_SEQ * KNN)       // 49152
#define TILE_E  192
#define N_TILES (N_EDGES / TILE_E)  // 256
#define GRID_MAIN 148
#define NTHREADS 384

__device__ float d_hv[L_SEQ * H];   // LN+W1 output (512 KB scratch)

// smem byte offsets (main kernel)
#define SM_W2HI 0
#define SM_W2LO 32768
#define SM_PHI  65536
#define SM_PLO  (65536 + TILE_E * 256)            // 114688
#define SM_B2   (SM_PLO + TILE_E * 256)           // 163840
#define SM_TOTAL (SM_B2 + 512 + 128)              // 164480 B

// ---------------------------------------------------------------------------
// helpers
// ---------------------------------------------------------------------------
__device__ __forceinline__ uint32_t smem_to_u32(const void* p) {
    uint32_t a;
    asm("{ .reg .u64 t; cvta.to.shared.u64 t, %1; cvt.u32.u64 %0, t; }"
        : "=r"(a) : "l"(p));
    return a;
}

// XOR swizzle on 16B chunks within a 256B row (conflict-free ldmatrix/STS)
__device__ __forceinline__ uint32_t swz(uint32_t row, uint32_t chunk) {
    return (chunk & 8u) | ((chunk ^ row) & 7u);
}

// split (a,b) fp32 pair into packed bf16x2 hi + bf16x2 lo (a -> low 16 bits)
__device__ __forceinline__ void split2(float a, float b, uint32_t& hi, uint32_t& lo) {
    uint32_t h;
    asm("cvt.rn.bf16x2.f32 %0, %1, %2;" : "=r"(h) : "f"(b), "f"(a));
    float ha = __uint_as_float(h << 16);
    float hb = __uint_as_float(h & 0xFFFF0000u);
    float la = a - ha;
    float lb = b - hb;
    asm("cvt.rn.bf16x2.f32 %0, %1, %2;" : "=r"(lo) : "f"(lb), "f"(la));
    hi = h;
}

__device__ __forceinline__ void ldsm_x4(uint32_t* r, uint32_t addr) {
    asm volatile("ldmatrix.sync.aligned.m8n8.x4.shared.b16 {%0,%1,%2,%3}, [%4];"
                 : "=r"(r[0]), "=r"(r[1]), "=r"(r[2]), "=r"(r[3]) : "r"(addr));
}

// NON-volatile mma: register constraints carry dependencies; ptxas may schedule.
__device__ __forceinline__ void mma_bf16(float* c, const uint32_t* a,
                                         uint32_t b0, uint32_t b1) {
    asm("mma.sync.aligned.m16n8k16.row.col.f32.bf16.bf16.f32 "
        "{%0,%1,%2,%3}, {%4,%5,%6,%7}, {%8,%9}, {%0,%1,%2,%3};"
        : "+f"(c[0]), "+f"(c[1]), "+f"(c[2]), "+f"(c[3])
        : "r"(a[0]), "r"(a[1]), "r"(a[2]), "r"(a[3]), "r"(b0), "r"(b1));
}

// ---------------------------------------------------------------------------
// Kernel 1: LayerNorm + Linear1 -> d_hv.  4 rows/block, 128 threads, 256 blocks.
// ---------------------------------------------------------------------------
__global__ void __launch_bounds__(128) ln_w1_kernel(
    const float* __restrict__ hV, const float* __restrict__ W1,
    const float* __restrict__ b1, const float* __restrict__ ln_scale,
    const float* __restrict__ ln_bias) {
    __shared__ float xs[4][H];
    int t = threadIdx.x, w = t >> 5, lane = t & 31;
    int i0 = blockIdx.x * 4;

    float4 g = reinterpret_cast<const float4*>(ln_scale)[lane];
    float4 c = reinterpret_cast<const float4*>(ln_bias)[lane];

    {
        int r = w;   // one row per warp
        float4 x = reinterpret_cast<const float4*>(hV + (size_t)(i0 + r) * H)[lane];
        float s = x.x + x.y + x.z + x.w;
        #pragma unroll
        for (int off = 16; off; off >>= 1) s += __shfl_xor_sync(~0u, s, off);
        float mu = s * (1.0f / H);
        float4 d = make_float4(x.x - mu, x.y - mu, x.z - mu, x.w - mu);
        float sq = d.x * d.x + d.y * d.y + d.z * d.z + d.w * d.w;
        #pragma unroll
        for (int off = 16; off; off >>= 1) sq += __shfl_xor_sync(~0u, sq, off);
        float rs = rsqrtf(sq * (1.0f / H) + 1e-5f);
        float4 o = make_float4(d.x * rs * g.x + c.x, d.y * rs * g.y + c.y,
                               d.z * rs * g.z + c.z, d.w * rs * g.w + c.w);
        reinterpret_cast<float4*>(xs[r])[lane] = o;
    }
    __syncthreads();

    float acc[4];
    float bt = b1[t];
    #pragma unroll
    for (int r = 0; r < 4; r++) acc[r] = bt;
    const float4* wrow = reinterpret_cast<const float4*>(W1 + (size_t)t * H);
    #pragma unroll 8
    for (int q = 0; q < H / 4; q++) {
        float4 w4 = wrow[q];
        #pragma unroll
        for (int r = 0; r < 4; r++) {
            float4 x4 = reinterpret_cast<const float4*>(xs[r])[q];
            acc[r] += w4.x * x4.x + w4.y * x4.y + w4.z * x4.z + w4.w * x4.w;
        }
    }
    #pragma unroll
    for (int r = 0; r < 4; r++) d_hv[(size_t)(i0 + r) * H + t] = acc[r];
}

// ---------------------------------------------------------------------------
// Kernel 2: C[49152,128] = P @ W2^T via mma.sync bf16, 3-term split.
// 384 threads = 12 warps as 6(m) x 2(n): warp tile m32 x n64, K=128.
// mma issue order maximizes RAW distance (8 independent acc per group).
// ---------------------------------------------------------------------------
__global__ void __launch_bounds__(NTHREADS, 1) outer_w2_mma_kernel(
    const int* __restrict__ Eidx, const float* __restrict__ W2,
    const float* __restrict__ b2, float* __restrict__ out) {
    extern __shared__ char smemc[];
    const uint32_t sb = smem_to_u32(smemc);
    int t = threadIdx.x;
    int warp = t >> 5, lane = t & 31;
    int wm = warp >> 1;     // 0..5  m32 tile
    int wn = warp & 1;      // 0..1  n64 half

    // ---- stage W2 hi/lo (bf16, swizzled [o][h]) + b2 ----
    for (int g = t; g < 2048; g += NTHREADS) {
        int o = g >> 4;                // output feature row
        int ch = g & 15;               // 16B chunk within row
        const float4* w = reinterpret_cast<const float4*>(W2 + (size_t)o * H + ch * 8);
        float4 w0 = w[0], w1 = w[1];
        uint4 hi4, lo4;
        split2(w0.x, w0.y, hi4.x, lo4.x);
        split2(w0.z, w0.w, hi4.y, lo4.y);
        split2(w1.x, w1.y, hi4.z, lo4.z);
        split2(w1.z, w1.w, hi4.w, lo4.w);
        uint32_t off = (uint32_t)o * 256 + swz(o, ch) * 16;
        *reinterpret_cast<uint4*>(smemc + SM_W2HI + off) = hi4;
        *reinterpret_cast<uint4*>(smemc + SM_W2LO + off) = lo4;
    }
    if (t < 128) reinterpret_cast<float*>(smemc + SM_B2)[t] = b2[t];
    __syncthreads();

    // ldmatrix lane-address components for the two m16 subtiles
    const uint32_t m0 = (uint32_t)(wm * 32 + (lane & 15));
    const uint32_t m1 = m0 + 16;
    const uint32_t a_sel  = (uint32_t)(lane >> 4);
    const uint32_t b_row7 = (uint32_t)(lane & 7);
    const uint32_t b_rowoff = b_row7 * 256;
    const uint32_t b_sel  = (uint32_t)(lane >> 3);

    for (int tile = blockIdx.x; tile < N_TILES; tile += gridDim.x) {
        // ---- build P hi/lo in smem (gather); 2 threads per edge row ----
        {
            int m = t >> 1;                  // edge row in tile (0..191)
            int half = t & 1;                // h half (64 each)
            int e = tile * TILE_E + m;
            int i = (int)((unsigned)e / KNN);
            int j = __ldg(Eidx + e);
            const float4* pi = reinterpret_cast<const float4*>(
                d_hv + (size_t)i * H + half * 64);
            const float4* pj = reinterpret_cast<const float4*>(
                d_hv + (size_t)j * H + half * 64);
            uint32_t rowbase = (uint32_t)m * 256;
            #pragma unroll
            for (int q = 0; q < 8; q++) {
                float4 x0 = pi[2 * q], x1 = pi[2 * q + 1];
                float4 y0 = pj[2 * q], y1 = pj[2 * q + 1];
                uint4 hi4, lo4;
                split2(x0.x * y0.x, x0.y * y0.y, hi4.x, lo4.x);
                split2(x0.z * y0.z, x0.w * y0.w, hi4.y, lo4.y);
                split2(x1.x * y1.x, x1.y * y1.y, hi4.z, lo4.z);
                split2(x1.z * y1.z, x1.w * y1.w, hi4.w, lo4.w);
                uint32_t off = rowbase + swz((uint32_t)m, (uint32_t)(half * 8 + q)) * 16;
                *reinterpret_cast<uint4*>(smemc + SM_PHI + off) = hi4;
                *reinterpret_cast<uint4*>(smemc + SM_PLO + off) = lo4;
            }
        }
        __syncthreads();

        // ---- warp GEMM: m32 x n64, K=128, 3-term bf16 split ----
        float acc[2][8][4];
        #pragma unroll
        for (int s = 0; s < 2; s++)
            #pragma unroll
            for (int nt = 0; nt < 8; nt++)
                #pragma unroll
                for (int q = 0; q < 4; q++) acc[s][nt][q] = 0.0f;

        #pragma unroll
        for (int kp = 0; kp < 4; kp++) {        // k32 steps
            // A fragments: [subtile][k16 half]
            uint32_t ah[2][2][4], al[2][2][4];
            #pragma unroll
            for (int s = 0; s < 2; s++) {
                uint32_t mrow = s ? m1 : m0;
                uint32_t rowoff = mrow * 256;
                #pragma unroll
                for (int ss = 0; ss < 2; ss++) {
                    uint32_t chunkA = (uint32_t)(4 * kp + 2 * ss) + a_sel;
                    uint32_t aaddr = sb + SM_PHI + rowoff + swz(mrow, chunkA) * 16;
                    ldsm_x4(ah[s][ss], aaddr);
                    ldsm_x4(al[s][ss], aaddr + (SM_PLO - SM_PHI));
                }
            }
            uint32_t chunkB = (uint32_t)(kp * 4) + b_sel;
            uint32_t bcol = swz(b_row7, chunkB) * 16;

            // B fragments in chunks of 4 nt; mma grouped by term (8 indep acc)
            #pragma unroll
            for (int nc = 0; nc < 2; nc++) {
                uint32_t bh[4][4], bl[4][4];
                #pragma unroll
                for (int q = 0; q < 4; q++) {
                    uint32_t o8 = (uint32_t)(wn * 8 + nc * 4 + q);
                    uint32_t baddr = sb + SM_W2HI + o8 * 2048 + b_rowoff + bcol;
                    ldsm_x4(bh[q], baddr);
                    ldsm_x4(bl[q], baddr + (SM_W2LO - SM_W2HI));
                }
                #pragma unroll
                for (int kh = 0; kh < 2; kh++) {
                    // term 1: hi * hi
                    #pragma unroll
                    for (int q = 0; q < 4; q++)
                        #pragma unroll
                        for (int s = 0; s < 2; s++)
                            mma_bf16(acc[s][nc * 4 + q], ah[s][kh],
                                     bh[q][2 * kh], bh[q][2 * kh + 1]);
                    // term 2: hi * lo
                    #pragma unroll
                    for (int q = 0; q < 4; q++)
                        #pragma unroll
                        for (int s = 0; s < 2; s++)
                            mma_bf16(acc[s][nc * 4 + q], ah[s][kh],
                                     bl[q][2 * kh], bl[q][2 * kh + 1]);
                    // term 3: lo * hi
                    #pragma unroll
                    for (int q = 0; q < 4; q++)
                        #pragma unroll
                        for (int s = 0; s < 2; s++)
                            mma_bf16(acc[s][nc * 4 + q], al[s][kh],
                                     bh[q][2 * kh], bh[q][2 * kh + 1]);
                }
            }
        }

        // ---- epilogue: + b2, store ----
        #pragma unroll
        for (int s = 0; s < 2; s++) {
            int r0 = tile * TILE_E + wm * 32 + s * 16 + (lane >> 2);
            int cbase = wn * 64 + (lane & 3) * 2;
            float* orow0 = out + (size_t)r0 * H;
            float* orow1 = orow0 + 8 * H;
            #pragma unroll
            for (int nt = 0; nt < 8; nt++) {
                float2 bb = *reinterpret_cast<const float2*>(
                    smemc + SM_B2 + (wn * 64 + nt * 8 + (lane & 3) * 2) * 4);
                float2 v0 = make_float2(acc[s][nt][0] + bb.x, acc[s][nt][1] + bb.y);
                float2 v1 = make_float2(acc[s][nt][2] + bb.x, acc[s][nt][3] + bb.y);
                *reinterpret_cast<float2*>(orow0 + nt * 8 + cbase) = v0;
                *reinterpret_cast<float2*>(orow1 + nt * 8 + cbase) = v1;
            }
        }
        __syncthreads();   // all warps done reading sP before next build
    }
}

// ---------------------------------------------------------------------------
extern "C" void kernel_launch(void* const* d_in, const int* in_sizes, int n_in,
                              void* d_out, int out_size) {
    const float* hV       = (const float*)d_in[0];
    const int*   Eidx     = (const int*)d_in[1];
    const float* W1       = (const float*)d_in[2];
    const float* b1       = (const float*)d_in[3];
    const float* W2       = (const float*)d_in[4];
    const float* b2       = (const float*)d_in[5];
    const float* ln_scale = (const float*)d_in[6];
    const float* ln_bias  = (const float*)d_in[7];
    float* out = (float*)d_out;

    cudaFuncSetAttribute(outer_w2_mma_kernel,
                         cudaFuncAttributeMaxDynamicSharedMemorySize, SM_TOTAL);

    ln_w1_kernel<<<L_SEQ / 4, 128>>>(hV, W1, b1, ln_scale, ln_bias);
    outer_w2_mma_kernel<<<GRID_MAIN, NTHREADS, SM_TOTAL>>>(Eidx, W2, b2, out);
}